// round 4
// baseline (speedup 1.0000x reference)
#include <cuda_runtime.h>
#include <cuda_fp16.h>
#include <cstdint>

#define INPUTDIM 512
#define DEG 8
#define OUTDIM 64
#define DEGK (DEG - 1)                 // degrees 1..7 in the GEMM
#define KDIM2 (INPUTDIM * DEGK)        // 3584

// ---------------- scratch (static device globals; no allocation) ----------------
__device__ __half  d_Bh[KDIM2 * OUTDIM];   // repacked coeffs [k'=i*7+(d-1)][o], fp16
__device__ float   d_pmin[2048], d_pmax[2048];
__device__ float   d_bias2[OUTDIM];        // bias + sum_i C[o,i,0]
__device__ float2  d_ab;                   // xn = a*x + b

#define MM_BLOCKS 2048
#define BIAS_BLK  MM_BLOCKS            // 64 blocks
#define PREP_BLK  (MM_BLOCKS + OUTDIM) // 32 blocks
#define MP_GRID   (PREP_BLK + 32)

// ---------------- kernel 1: fused minmax partials + bias fold + coeff repack ----------------
__global__ __launch_bounds__(256) void k_mp(const float4* __restrict__ x4, int n4,
                                            const float* __restrict__ coeffs,
                                            const float* __restrict__ bias) {
    const int bid = blockIdx.x, tid = threadIdx.x;
    __shared__ float sred[64];

    if (bid < MM_BLOCKS) {
        // ---- min/max partial over grid-stride slice ----
        float lmin = 3.4e38f, lmax = -3.4e38f;
        int stride = MM_BLOCKS * 256;
        for (int idx = bid * 256 + tid; idx < n4; idx += stride) {
            float4 v = x4[idx];
            lmin = fminf(lmin, fminf(fminf(v.x, v.y), fminf(v.z, v.w)));
            lmax = fmaxf(lmax, fmaxf(fmaxf(v.x, v.y), fmaxf(v.z, v.w)));
        }
        #pragma unroll
        for (int o = 16; o; o >>= 1) {
            lmin = fminf(lmin, __shfl_xor_sync(0xFFFFFFFFu, lmin, o));
            lmax = fmaxf(lmax, __shfl_xor_sync(0xFFFFFFFFu, lmax, o));
        }
        int w = tid >> 5;
        if ((tid & 31) == 0) { sred[w] = lmin; sred[8 + w] = lmax; }
        __syncthreads();
        if (tid == 0) {
            #pragma unroll
            for (int i = 1; i < 8; i++) {
                lmin = fminf(lmin, sred[i]);
                lmax = fmaxf(lmax, sred[8 + i]);
            }
            d_pmin[bid] = lmin; d_pmax[bid] = lmax;
        }
    } else if (bid < PREP_BLK) {
        // ---- bias fold: d_bias2[o] = bias[o] + sum_i coeffs[o][i][0] ----
        const int o = bid - BIAS_BLK;
        float s = coeffs[(o * INPUTDIM + tid) * DEG]
                + coeffs[(o * INPUTDIM + tid + 256) * DEG];
        #pragma unroll
        for (int off = 16; off; off >>= 1) s += __shfl_xor_sync(0xFFFFFFFFu, s, off);
        if ((tid & 31) == 0) sred[tid >> 5] = s;
        __syncthreads();
        if (tid == 0) {
            #pragma unroll
            for (int i = 1; i < 8; i++) s += sred[i];
            d_bias2[o] = bias[o] + s;
        }
    } else {
        // ---- coeff repack: d_Bh[k'*64+o] = fp16(coeffs[o][i][d]), k'=i*7+d-1 ----
        int idx = (bid - PREP_BLK) * 256 + tid;     // 8192 threads
        for (; idx < KDIM2 * OUTDIM; idx += 32 * 256) {
            int k = idx >> 6, o = idx & 63;
            int i = k / 7, d = k - i * 7 + 1;
            d_Bh[idx] = __float2half(coeffs[(o * INPUTDIM + i) * DEG + d]);
        }
    }
}

// ---------------- kernel 2: reduce partials -> scale/offset ----------------
__global__ __launch_bounds__(1024) void k_scale() {
    __shared__ float smn[32], smx[32];
    int tid = threadIdx.x;
    float lmin = fminf(d_pmin[tid], d_pmin[tid + 1024]);
    float lmax = fmaxf(d_pmax[tid], d_pmax[tid + 1024]);
    #pragma unroll
    for (int o = 16; o; o >>= 1) {
        lmin = fminf(lmin, __shfl_xor_sync(0xFFFFFFFFu, lmin, o));
        lmax = fmaxf(lmax, __shfl_xor_sync(0xFFFFFFFFu, lmax, o));
    }
    if ((tid & 31) == 0) { smn[tid >> 5] = lmin; smx[tid >> 5] = lmax; }
    __syncthreads();
    if (tid == 0) {
        #pragma unroll
        for (int i = 1; i < 32; i++) {
            lmin = fminf(lmin, smn[i]);
            lmax = fmaxf(lmax, smx[i]);
        }
        float a = 2.0f / (lmax - lmin);
        d_ab = make_float2(a, -a * lmin - 1.0f);
    }
}

// ---------------- PTX helpers (sm_80-class; legal in compute_103 PTX) ----------------
__device__ __forceinline__ void ldsm_x4(unsigned* r, unsigned addr) {
    asm volatile("ldmatrix.sync.aligned.m8n8.x4.shared.b16 {%0,%1,%2,%3}, [%4];\n"
                 : "=r"(r[0]), "=r"(r[1]), "=r"(r[2]), "=r"(r[3]) : "r"(addr));
}
__device__ __forceinline__ void ldsm_x4_trans(unsigned* r, unsigned addr) {
    asm volatile("ldmatrix.sync.aligned.m8n8.x4.trans.shared.b16 {%0,%1,%2,%3}, [%4];\n"
                 : "=r"(r[0]), "=r"(r[1]), "=r"(r[2]), "=r"(r[3]) : "r"(addr));
}
__device__ __forceinline__ void mma16816(float* c, const unsigned* a, unsigned b0, unsigned b1) {
    asm volatile(
        "mma.sync.aligned.m16n8k16.row.col.f32.f16.f16.f32 "
        "{%0,%1,%2,%3}, {%4,%5,%6,%7}, {%8,%9}, {%0,%1,%2,%3};\n"
        : "+f"(c[0]), "+f"(c[1]), "+f"(c[2]), "+f"(c[3])
        : "r"(a[0]), "r"(a[1]), "r"(a[2]), "r"(a[3]), "r"(b0), "r"(b1));
}
__device__ __forceinline__ void cp_async16(uint32_t dst, const void* src) {
    asm volatile("cp.async.cg.shared.global [%0], [%1], 16;" :: "r"(dst), "l"(src));
}
#define CP_COMMIT()  asm volatile("cp.async.commit_group;" ::: "memory")
#define CP_WAIT(n)   asm volatile("cp.async.wait_group %0;" :: "n"(n) : "memory")

// ---------------- kernel 3: fused Legendre + GEMM (K = 3584) ----------------
#define BM 128
#define IC 16                     // inputs per stage
#define KC (IC * DEGK)            // 112 k's per stage (7 x k16)
#define NST (INPUTDIM / IC)       // 32 stages
#define A_STRIDE 240              // 224B data + 16 pad
#define B_STRIDE 144              // 128B data + 16 pad
#define A_BYTES (BM * A_STRIDE)   // 30720
#define B_BYTES (KC * B_STRIDE)   // 16128
#define SMEM_BYTES (A_BYTES + B_BYTES)   // 46848

__global__ __launch_bounds__(256, 2) void k_main(const float* __restrict__ x,
                                                 float* __restrict__ out) {
    extern __shared__ __align__(128) unsigned char sm[];
    __shared__ float sbias[OUTDIM];

    const uint32_t smem_u32 = (uint32_t)__cvta_generic_to_shared(sm);
    const int tid  = threadIdx.x;
    const int warp = tid >> 5, lane = tid & 31;
    const int n0   = blockIdx.x * BM;
    const float2 ab = d_ab;

    if (tid < OUTDIM) sbias[tid] = d_bias2[tid];

    float acc[8][4];
    #pragma unroll
    for (int i = 0; i < 8; i++)
        #pragma unroll
        for (int j = 0; j < 4; j++) acc[i][j] = 0.f;

    // producer mappings
    const int arow  = tid >> 1;                // 0..127
    const int ihalf = tid & 1;                 // which 8 of the 16 i's
    const float* xrow = x + (size_t)(n0 + arow) * INPUTDIM + ihalf * 8;
    unsigned char* adst0 = sm + arow * A_STRIDE + ihalf * 112;
    // B: 896 16B-chunks; threads 0..223 copy 4 each
    const int bc0 = tid * 4;
    const uint32_t b_dst0 = smem_u32 + A_BYTES + (bc0 >> 3) * B_STRIDE + (bc0 & 7) * 16;

    // consumer bases
    const uint32_t a_ld0 = smem_u32 + (warp * 16 + (lane & 15)) * A_STRIDE + ((lane >> 4) & 1) * 16;
    const uint32_t b_ld0 = smem_u32 + A_BYTES + (lane & 15) * B_STRIDE + ((lane >> 4) & 1) * 16;

    for (int s = 0; s < NST; s++) {
        // ---- produce B: 112 k-rows x 64 o fp16, contiguous in d_Bh ----
        if (tid < 224) {
            const __half* src = d_Bh + (size_t)s * KC * OUTDIM + bc0 * 8;
            cp_async16(b_dst0,      src);
            cp_async16(b_dst0 + 16, src + 8);      // chunks bc0, bc0+1
            cp_async16(b_dst0 + 32, src + 16);     // (bc0&7)+3 <= 7 since bc0%8==0 mod 4... bc0 multiple of 4
            cp_async16(b_dst0 + 48, src + 24);
            CP_COMMIT();
        }

        // ---- produce A: Legendre P1..P7 for 8 x's -> 112B ----
        {
            float4 v0 = *(const float4*)(xrow + s * IC);
            float4 v1 = *(const float4*)(xrow + s * IC + 4);
            float xs[8] = {v0.x, v0.y, v0.z, v0.w, v1.x, v1.y, v1.z, v1.w};
            __align__(16) __half ph[56];
            #pragma unroll
            for (int q = 0; q < 8; q++) {
                float t = fmaf(ab.x, xs[q], ab.y);
                float P[8];
                P[0] = 1.f; P[1] = t;
                #pragma unroll
                for (int nr = 2; nr < 8; nr++)
                    P[nr] = ((2.f * nr - 1.f) * t * P[nr - 1] - (nr - 1.f) * P[nr - 2]) * (1.f / nr);
                #pragma unroll
                for (int dd = 1; dd < 8; dd++)
                    ph[q * 7 + dd - 1] = __float2half_rn(P[dd]);
            }
            #pragma unroll
            for (int q = 0; q < 7; q++)
                *(uint4*)(adst0 + q * 16) = *(uint4*)(&ph[q * 8]);
        }

        CP_WAIT(0);
        __syncthreads();     // stage visible

        // ---- consume: each warp m16 x n64, K=112 ----
        #pragma unroll
        for (int kk = 0; kk < 7; kk++) {
            unsigned a[4];
            ldsm_x4(a, a_ld0 + kk * 32);
            #pragma unroll
            for (int j = 0; j < 4; j++) {
                unsigned b[4];
                ldsm_x4_trans(b, b_ld0 + kk * 16 * B_STRIDE + j * 32);
                mma16816(acc[2 * j],     a, b[0], b[1]);
                mma16816(acc[2 * j + 1], a, b[2], b[3]);
            }
        }
        __syncthreads();     // all reads done before next overwrite
    }

    // ---- epilogue: add folded bias, write fp32 ----
    const int g = lane >> 2, t4 = lane & 3;
    const int row0 = n0 + warp * 16 + g;
    #pragma unroll
    for (int nt = 0; nt < 8; nt++) {
        int col = nt * 8 + 2 * t4;
        float b0 = sbias[col], b1 = sbias[col + 1];
        *(float2*)(out + (size_t)row0 * OUTDIM + col) =
            make_float2(acc[nt][0] + b0, acc[nt][1] + b1);
        *(float2*)(out + (size_t)(row0 + 8) * OUTDIM + col) =
            make_float2(acc[nt][2] + b0, acc[nt][3] + b1);
    }
}

// ---------------- launch ----------------
extern "C" void kernel_launch(void* const* d_in, const int* in_sizes, int n_in,
                              void* d_out, int out_size) {
    const float* x      = (const float*)d_in[0];
    const float* coeffs = (const float*)d_in[1];
    const float* bias   = (const float*)d_in[2];
    float* out = (float*)d_out;

    const int nx = in_sizes[0];            // 33554432
    const int Nrows = nx / INPUTDIM;       // 65536

    cudaFuncSetAttribute(k_main, cudaFuncAttributeMaxDynamicSharedMemorySize, SMEM_BYTES);

    k_mp<<<MP_GRID, 256>>>((const float4*)x, nx / 4, coeffs, bias);
    k_scale<<<1, 1024>>>();
    k_main<<<Nrows / BM, 256, SMEM_BYTES>>>(x, out);
}